// round 1
// baseline (speedup 1.0000x reference)
#include <cuda_runtime.h>
#include <cuda_bf16.h>

#define BATCH 1024
#define NUM_CLASS 100000
#define FEAT_DIM 128

// Per-row squared distance scratch (allocation-free; rewritten every launch).
__device__ float g_row_dist[BATCH];

// Kernel 1: one block per batch row, 128 threads (one per feature dim).
// d_i = sum(x_i^2) + sum(c_l^2) - 2 * dot(x_i, c_l), matching the reference's
// expanded formula.
__global__ void __launch_bounds__(FEAT_DIM) row_dist_kernel(
    const float* __restrict__ x,
    const int* __restrict__ labels,
    const float* __restrict__ centers) {
    const int row = blockIdx.x;
    const int t = threadIdx.x;

    const int l = labels[row];
    const float xv = x[row * FEAT_DIM + t];
    const float cv = centers[(long long)l * FEAT_DIM + t];

    float sx = xv * xv;
    float sc = cv * cv;
    float sxc = xv * cv;

    // Warp reduce (4 warps of 32)
    #pragma unroll
    for (int off = 16; off > 0; off >>= 1) {
        sx  += __shfl_down_sync(0xFFFFFFFFu, sx,  off);
        sc  += __shfl_down_sync(0xFFFFFFFFu, sc,  off);
        sxc += __shfl_down_sync(0xFFFFFFFFu, sxc, off);
    }

    __shared__ float s_sx[4], s_sc[4], s_sxc[4];
    const int wid = t >> 5;
    const int lid = t & 31;
    if (lid == 0) {
        s_sx[wid] = sx;
        s_sc[wid] = sc;
        s_sxc[wid] = sxc;
    }
    __syncthreads();

    if (t == 0) {
        float tsx = s_sx[0] + s_sx[1] + s_sx[2] + s_sx[3];
        float tsc = s_sc[0] + s_sc[1] + s_sc[2] + s_sc[3];
        float tsxc = s_sxc[0] + s_sxc[1] + s_sxc[2] + s_sxc[3];
        g_row_dist[row] = tsx + tsc - 2.0f * tsxc;
    }
}

// Kernel 2: single block reduces the 1024 clipped distances to the scalar loss.
__global__ void __launch_bounds__(BATCH) reduce_kernel(float* __restrict__ out) {
    const int t = threadIdx.x;

    float v = g_row_dist[t];
    // clip(d, 1e-12, 1e12)
    v = fminf(fmaxf(v, 1e-12f), 1e12f);

    // Warp reduce (32 warps)
    #pragma unroll
    for (int off = 16; off > 0; off >>= 1)
        v += __shfl_down_sync(0xFFFFFFFFu, v, off);

    __shared__ float s_partial[32];
    const int wid = t >> 5;
    const int lid = t & 31;
    if (lid == 0) s_partial[wid] = v;
    __syncthreads();

    if (wid == 0) {
        float w = s_partial[lid];
        #pragma unroll
        for (int off = 16; off > 0; off >>= 1)
            w += __shfl_down_sync(0xFFFFFFFFu, w, off);
        if (lid == 0) {
            // All (B*C - B) masked-out zeros clamp to 1e-12 and are summed too.
            const float zero_term =
                (float)(((double)BATCH * (double)NUM_CLASS - (double)BATCH) * 1e-12);
            out[0] = (w + zero_term) / (float)BATCH;
        }
    }
}

extern "C" void kernel_launch(void* const* d_in, const int* in_sizes, int n_in,
                              void* d_out, int out_size) {
    // Map inputs by element count (robust to ordering): x=131072 f32,
    // labels=1024 i32, centers=12800000 f32.
    const float* x = nullptr;
    const int* labels = nullptr;
    const float* centers = nullptr;
    for (int i = 0; i < n_in; i++) {
        if (in_sizes[i] == BATCH * FEAT_DIM) x = (const float*)d_in[i];
        else if (in_sizes[i] == BATCH) labels = (const int*)d_in[i];
        else if (in_sizes[i] == NUM_CLASS * FEAT_DIM) centers = (const float*)d_in[i];
    }

    float* out = (float*)d_out;
    row_dist_kernel<<<BATCH, FEAT_DIM>>>(x, labels, centers);
    reduce_kernel<<<1, BATCH>>>(out);
}

// round 3
// speedup vs baseline: 1.1111x; 1.1111x over previous
#include <cuda_runtime.h>
#include <cuda_bf16.h>

#define BATCH 1024
#define NUM_CLASS 100000
#define FEAT_DIM 128
#define ROWS_PER_BLOCK 4
#define NBLOCKS (BATCH / ROWS_PER_BLOCK)

// Fixed-point scale: 2^28. Max accumulated value ~1024 * ~400 * 2^28 ~ 1.1e14,
// far below 2^63. Per-term quantization error 2^-28 ~ 3.7e-9 (order-independent
// => bitwise deterministic).
#define FP_SCALE 268435456.0  // 2^28

// Persistent device state (zero-initialized at module load; every launch
// leaves them back at zero, so graph replays are correct).
__device__ unsigned long long g_acc = 0ull;
__device__ unsigned int g_done = 0u;

// 256 blocks x 128 threads. One WARP per batch row: 32 lanes x float4 = 128
// features. d = sum(x^2) + sum(c^2) - 2*dot(x,c); clip; per-block fixed-point
// atomic; last block finalizes.
__global__ void __launch_bounds__(128) center_loss_kernel(
    const float4* __restrict__ x4,
    const int* __restrict__ labels,
    const float4* __restrict__ c4,
    float* __restrict__ out) {
    const int t = threadIdx.x;
    const int wid = t >> 5;
    const int lid = t & 31;
    const int row = blockIdx.x * ROWS_PER_BLOCK + wid;

    const int l = labels[row];
    // Row layout: FEAT_DIM floats = 32 float4s per row.
    const float4 xv = x4[row * 32 + lid];
    const float4 cv = c4[(long long)l * 32 + lid];

    float sx  = xv.x * xv.x + xv.y * xv.y + xv.z * xv.z + xv.w * xv.w;
    float sc  = cv.x * cv.x + cv.y * cv.y + cv.z * cv.z + cv.w * cv.w;
    float sxc = xv.x * cv.x + xv.y * cv.y + xv.z * cv.z + xv.w * cv.w;

    #pragma unroll
    for (int off = 16; off > 0; off >>= 1) {
        sx  += __shfl_down_sync(0xFFFFFFFFu, sx,  off);
        sc  += __shfl_down_sync(0xFFFFFFFFu, sc,  off);
        sxc += __shfl_down_sync(0xFFFFFFFFu, sxc, off);
    }

    // Per-row clipped distance -> fixed-point, combined across the 4 warps.
    __shared__ unsigned long long s_q[ROWS_PER_BLOCK];
    if (lid == 0) {
        float d = sx + sc - 2.0f * sxc;
        d = fminf(fmaxf(d, 1e-12f), 1e12f);
        s_q[wid] = (unsigned long long)llrint((double)d * FP_SCALE);
    }
    __syncthreads();

    if (t == 0) {
        unsigned long long q = s_q[0] + s_q[1] + s_q[2] + s_q[3];
        atomicAdd(&g_acc, q);
        __threadfence();

        unsigned int ticket = atomicAdd(&g_done, 1u);
        if (ticket == (unsigned int)(gridDim.x - 1)) {
            unsigned long long total = g_acc;
            const double zero_term =
                ((double)BATCH * (double)NUM_CLASS - (double)BATCH) * 1e-12;
            double loss = ((double)total / FP_SCALE + zero_term) / (double)BATCH;
            out[0] = (float)loss;
            // Reset for the next graph replay.
            g_acc = 0ull;
            __threadfence();
            g_done = 0u;
        }
    }
}

extern "C" void kernel_launch(void* const* d_in, const int* in_sizes, int n_in,
                              void* d_out, int out_size) {
    const float* x = nullptr;
    const int* labels = nullptr;
    const float* centers = nullptr;
    for (int i = 0; i < n_in; i++) {
        if (in_sizes[i] == BATCH * FEAT_DIM) x = (const float*)d_in[i];
        else if (in_sizes[i] == BATCH) labels = (const int*)d_in[i];
        else if (in_sizes[i] == NUM_CLASS * FEAT_DIM) centers = (const float*)d_in[i];
    }

    center_loss_kernel<<<NBLOCKS, 128>>>(
        (const float4*)x, labels, (const float4*)centers, (float*)d_out);
}